// round 5
// baseline (speedup 1.0000x reference)
#include <cuda_runtime.h>
#include <math.h>

#define TT   1024
#define DD   256
#define HH   256
#define LDP  1024

// Scratch (static device globals; no allocation)
__device__ float    g_P[TT*LDP];   // cols [0,256)=k(elu) [256,512)=q(elu) [512,768)=v [768,1024)=skip
__device__ float    g_A[TT*TT];    // masked scores (lower-tri tiles valid)
__device__ float    g_O[TT*HH];    // attention output (numer/denom)
__device__ float    g_H1[TT*HH];
__device__ float    g_H2[TT*HH];
__device__ float    g_H3[TT*HH];
__device__ unsigned g_M[TT*32];    // bit (ti,ki): coeff of kv_{ki+1} in scan result[ti+1]
__device__ float    g_den[TT];
__device__ float    g_ksum[TT], g_qsum[TT];

// Scan simulation scratch
__device__ unsigned g_Dm[2048*32];
__device__ unsigned g_Sm[2048*32];
__device__ int      g_Dg[2048];

// ---------------------------------------------------------------------------
// Exact simulation of jax.lax.associative_scan's recursive bracketing on
// 1024-bit coefficient masks. Also zeroes the rowsum accumulators.
// ---------------------------------------------------------------------------
__global__ void scan_mask_kernel(const int* __restrict__ start, const int* __restrict__ done) {
    const int n[11]   = {1025,512,256,128,64,32,16,8,4,2,1};
    const int off[11] = {0,1025,1537,1793,1921,1985,2017,2033,2041,2045,2047};
    int tid = threadIdx.x;

    if (tid < 1024) { g_ksum[tid] = 0.f; g_qsum[tid] = 0.f; }

    for (int idx = tid; idx < 1025*32; idx += blockDim.x) {
        int i = idx >> 5, w = idx & 31;
        unsigned m = 0;
        if (i > 0 && ((i-1) >> 5) == w) m = 1u << ((i-1) & 31);
        g_Dm[idx] = m;
        if (w == 0) g_Dg[i] = (start[i] ? 1 : 0) | (done[i] ? 2 : 0);
    }
    __syncthreads();

    for (int d = 0; d < 10; d++) {
        int nn = n[d+1];
        int src = off[d], dst = off[d+1];
        for (int idx = tid; idx < nn*32; idx += blockDim.x) {
            int i = idx >> 5, w = idx & 31;
            int gb = g_Dg[src + 2*i + 1];
            unsigned m = 0;
            if (gb & 1) m |= g_Dm[(src + 2*i    )*32 + w];
            if (gb & 2) m |= g_Dm[(src + 2*i + 1)*32 + w];
            g_Dm[(dst + i)*32 + w] = m;
            if (w == 0) g_Dg[dst + i] = gb;
        }
        __syncthreads();
    }

    for (int w = tid; w < 32; w += blockDim.x)
        g_Sm[off[10]*32 + w] = g_Dm[off[10]*32 + w];
    __syncthreads();

    for (int d = 9; d >= 0; d--) {
        int nd = n[d];
        int src = off[d], o = off[d+1];
        for (int idx = tid; idx < nd*32; idx += blockDim.x) {
            int pos = idx >> 5, w = idx & 31;
            unsigned m;
            if (pos == 0) {
                m = g_Dm[src*32 + w];
            } else if (pos & 1) {
                m = g_Sm[(o + (pos >> 1))*32 + w];
            } else {
                int i = (pos >> 1) - 1;
                int gb = g_Dg[src + pos];
                m = 0;
                if (gb & 1) m |= g_Sm[(o + i)*32 + w];
                if (gb & 2) m |= g_Dm[(src + pos)*32 + w];
            }
            g_Sm[(src + pos)*32 + w] = m;
        }
        __syncthreads();
    }

    for (int idx = tid; idx < 1024*32; idx += blockDim.x) {
        int t = idx >> 5, w = idx & 31;
        g_M[idx] = g_Sm[(t + 1)*32 + w];
    }
}

// ---------------------------------------------------------------------------
// Double-buffered GEMM cores. One __syncthreads per K-step; next K-step's
// global loads issued before compute so latency hides under the FMAs.
// ---------------------------------------------------------------------------
__device__ __forceinline__ void microfma44(float acc[4][4], float4 a, float4 b) {
    acc[0][0] += a.x*b.x; acc[0][1] += a.x*b.y; acc[0][2] += a.x*b.z; acc[0][3] += a.x*b.w;
    acc[1][0] += a.y*b.x; acc[1][1] += a.y*b.y; acc[1][2] += a.y*b.z; acc[1][3] += a.y*b.w;
    acc[2][0] += a.z*b.x; acc[2][1] += a.z*b.y; acc[2][2] += a.z*b.z; acc[2][3] += a.z*b.w;
    acc[3][0] += a.w*b.x; acc[3][1] += a.w*b.y; acc[3][2] += a.w*b.z; acc[3][3] += a.w*b.w;
}
__device__ __forceinline__ void microfma42(float acc[4][2], float4 a, float2 b) {
    acc[0][0] += a.x*b.x; acc[0][1] += a.x*b.y;
    acc[1][0] += a.y*b.x; acc[1][1] += a.y*b.y;
    acc[2][0] += a.z*b.x; acc[2][1] += a.z*b.y;
    acc[3][0] += a.w*b.x; acc[3][1] += a.w*b.y;
}

// C[64x64] = A[64xK] * B[64xK]^T  (both k-contiguous rows)
__device__ __forceinline__ void gemm_TT64(
    const float* __restrict__ A, int lda, int m0,
    const float* __restrict__ B, int ldb, int n0,
    int K, float acc[4][4],
    float (*As)[16][64], float (*Bs)[16][64],
    int tid, int tx, int ty)
{
    int row = tid >> 2, c4 = (tid & 3) << 2;
    const float* pA = A + (size_t)(m0 + row) * lda + c4;
    const float* pB = B + (size_t)(n0 + row) * ldb + c4;
    float4 av = *(const float4*)pA;
    float4 bv = *(const float4*)pB;
    int buf = 0;
    As[0][c4+0][row]=av.x; As[0][c4+1][row]=av.y; As[0][c4+2][row]=av.z; As[0][c4+3][row]=av.w;
    Bs[0][c4+0][row]=bv.x; Bs[0][c4+1][row]=bv.y; Bs[0][c4+2][row]=bv.z; Bs[0][c4+3][row]=bv.w;
    __syncthreads();
    for (int k0 = 16; k0 < K; k0 += 16) {
        av = *(const float4*)(pA + k0);
        bv = *(const float4*)(pB + k0);
#pragma unroll
        for (int kk = 0; kk < 16; kk++) {
            float4 a = *(const float4*)&As[buf][kk][ty*4];
            float4 b = *(const float4*)&Bs[buf][kk][tx*4];
            microfma44(acc, a, b);
        }
        int nb = buf ^ 1;
        As[nb][c4+0][row]=av.x; As[nb][c4+1][row]=av.y; As[nb][c4+2][row]=av.z; As[nb][c4+3][row]=av.w;
        Bs[nb][c4+0][row]=bv.x; Bs[nb][c4+1][row]=bv.y; Bs[nb][c4+2][row]=bv.z; Bs[nb][c4+3][row]=bv.w;
        __syncthreads();
        buf = nb;
    }
#pragma unroll
    for (int kk = 0; kk < 16; kk++) {
        float4 a = *(const float4*)&As[buf][kk][ty*4];
        float4 b = *(const float4*)&Bs[buf][kk][tx*4];
        microfma44(acc, a, b);
    }
}

// C[64x32] = A[64xK] * B[32xK]^T   (both k-contiguous rows)
__device__ __forceinline__ void gemm_TT32(
    const float* __restrict__ A, int lda, int m0,
    const float* __restrict__ B, int ldb, int n0,
    int K, float acc[4][2],
    float (*As)[16][64], float (*Bs)[16][32],
    int tid, int tx, int ty)
{
    int rowA = tid >> 2, c4 = (tid & 3) << 2;
    int rowB = tid >> 2;   // only tid<128 loads B (rows 0..31)
    const float* pA = A + (size_t)(m0 + rowA) * lda + c4;
    const float* pB = B + (size_t)(n0 + rowB) * ldb + c4;
    float4 av = *(const float4*)pA;
    float4 bv;
    if (tid < 128) bv = *(const float4*)pB;
    int buf = 0;
    As[0][c4+0][rowA]=av.x; As[0][c4+1][rowA]=av.y; As[0][c4+2][rowA]=av.z; As[0][c4+3][rowA]=av.w;
    if (tid < 128) {
        Bs[0][c4+0][rowB]=bv.x; Bs[0][c4+1][rowB]=bv.y; Bs[0][c4+2][rowB]=bv.z; Bs[0][c4+3][rowB]=bv.w;
    }
    __syncthreads();
    for (int k0 = 16; k0 < K; k0 += 16) {
        av = *(const float4*)(pA + k0);
        if (tid < 128) bv = *(const float4*)(pB + k0);
#pragma unroll
        for (int kk = 0; kk < 16; kk++) {
            float4 a = *(const float4*)&As[buf][kk][ty*4];
            float2 b = *(const float2*)&Bs[buf][kk][tx*2];
            microfma42(acc, a, b);
        }
        int nb = buf ^ 1;
        As[nb][c4+0][rowA]=av.x; As[nb][c4+1][rowA]=av.y; As[nb][c4+2][rowA]=av.z; As[nb][c4+3][rowA]=av.w;
        if (tid < 128) {
            Bs[nb][c4+0][rowB]=bv.x; Bs[nb][c4+1][rowB]=bv.y; Bs[nb][c4+2][rowB]=bv.z; Bs[nb][c4+3][rowB]=bv.w;
        }
        __syncthreads();
        buf = nb;
    }
#pragma unroll
    for (int kk = 0; kk < 16; kk++) {
        float4 a = *(const float4*)&As[buf][kk][ty*4];
        float2 b = *(const float2*)&Bs[buf][kk][tx*2];
        microfma42(acc, a, b);
    }
}

// C[64x32] = A[64xK] * B[Kx32]   (B row-major k x n)
__device__ __forceinline__ void gemm_TN32(
    const float* __restrict__ A, int lda, int m0,
    const float* __restrict__ B, int ldb, int n0,
    int K, float acc[4][2],
    float (*As)[16][64], float (*Bs)[16][32],
    int tid, int tx, int ty)
{
    int rowA = tid >> 2, c4 = (tid & 3) << 2;
    int kB = tid >> 3, cB = (tid & 7) << 2;  // tid<128: 16 k-rows x 32 cols
    const float* pA = A + (size_t)(m0 + rowA) * lda + c4;
    const float* pB = B + (size_t)kB * ldb + n0 + cB;
    float4 av = *(const float4*)pA;
    float4 bv;
    if (tid < 128) bv = *(const float4*)pB;
    int buf = 0;
    As[0][c4+0][rowA]=av.x; As[0][c4+1][rowA]=av.y; As[0][c4+2][rowA]=av.z; As[0][c4+3][rowA]=av.w;
    if (tid < 128) *(float4*)&Bs[0][kB][cB] = bv;
    __syncthreads();
    for (int k0 = 16; k0 < K; k0 += 16) {
        av = *(const float4*)(pA + k0);
        if (tid < 128) bv = *(const float4*)(pB + (size_t)k0 * ldb);
#pragma unroll
        for (int kk = 0; kk < 16; kk++) {
            float4 a = *(const float4*)&As[buf][kk][ty*4];
            float2 b = *(const float2*)&Bs[buf][kk][tx*2];
            microfma42(acc, a, b);
        }
        int nb = buf ^ 1;
        As[nb][c4+0][rowA]=av.x; As[nb][c4+1][rowA]=av.y; As[nb][c4+2][rowA]=av.z; As[nb][c4+3][rowA]=av.w;
        if (tid < 128) *(float4*)&Bs[nb][kB][cB] = bv;
        __syncthreads();
        buf = nb;
    }
#pragma unroll
    for (int kk = 0; kk < 16; kk++) {
        float4 a = *(const float4*)&As[buf][kk][ty*4];
        float2 b = *(const float2*)&Bs[buf][kk][tx*2];
        microfma42(acc, a, b);
    }
}

// ---------------------------------------------------------------------------
// Projections + fused k/q row sums.
// ---------------------------------------------------------------------------
__global__ void __launch_bounds__(256) proj_kernel(
    const float* __restrict__ X,
    const float* __restrict__ Wk, const float* __restrict__ Wq,
    const float* __restrict__ Wv, const float* __restrict__ Ws,
    const float* __restrict__ bskip)
{
    __shared__ float As[2][16][64], Bs[2][16][64];
    __shared__ float red[64][17];
    int tid = threadIdx.x, tx = tid & 15, ty = tid >> 4;
    int bx = blockIdx.x, by = blockIdx.y;
    int wsel = bx >> 2;
    const float* W = (wsel == 0) ? Wk : (wsel == 1) ? Wq : (wsel == 2) ? Wv : Ws;
    int n0 = (bx & 3) * 64;
    int m0 = by * 64;
    float acc[4][4] = {};
    gemm_TT64(X, DD, m0, W, DD, n0, DD, acc, As, Bs, tid, tx, ty);

    float rs[4] = {0.f, 0.f, 0.f, 0.f};
#pragma unroll
    for (int i = 0; i < 4; i++) {
        int t = m0 + ty * 4 + i;
        float4 vs;
        float* vp = (float*)&vs;
#pragma unroll
        for (int j = 0; j < 4; j++) {
            int c = n0 + tx * 4 + j;
            float v = acc[i][j];
            if (wsel < 2) v = (v > 0.f) ? v : expm1f(v);     // elu
            if (wsel == 3) v += bskip[c];
            vp[j] = v;
            rs[i] += v;
        }
        *(float4*)&g_P[(size_t)t * LDP + wsel * 256 + n0 + tx * 4] = vs;
    }
    if (wsel < 2) {
        __syncthreads();
#pragma unroll
        for (int i = 0; i < 4; i++) red[ty * 4 + i][tx] = rs[i];
        __syncthreads();
        if (tid < 64) {
            float s = 0.f;
#pragma unroll
            for (int x = 0; x < 16; x++) s += red[tid][x];
            atomicAdd((wsel == 0) ? &g_ksum[m0 + tid] : &g_qsum[m0 + tid], s);
        }
    }
}

// ---------------------------------------------------------------------------
// denom[t] = qsum[t] * sum_j mask(t,j)*ksum[j].  ksum staged in SMEM.
// ---------------------------------------------------------------------------
__global__ void denom_kernel() {
    __shared__ float ks[1024];
    int tid = threadIdx.x;
    for (int i = tid; i < 1024; i += 256) ks[i] = g_ksum[i];
    __syncthreads();
    int row  = blockIdx.x * 8 + (tid >> 5);
    int lane = tid & 31;
    unsigned bits = g_M[row * 32 + lane];
    float s = 0.f;
    while (bits) {
        int b = __ffs(bits) - 1;
        bits &= bits - 1;
        s += ks[lane * 32 + b];
    }
#pragma unroll
    for (int o = 16; o > 0; o >>= 1) s += __shfl_xor_sync(0xffffffffu, s, o);
    if (lane == 0) g_den[row] = s * g_qsum[row];
}

// ---------------------------------------------------------------------------
// Masked scores A = (Q K^T) * M. Only lower-triangular tiles computed.
// ---------------------------------------------------------------------------
__global__ void __launch_bounds__(256) scores_kernel() {
    int bi = blockIdx.x, bt = blockIdx.y;
    if (bi > bt) return;
    __shared__ float As[2][16][64], Bs[2][16][64];
    int tid = threadIdx.x, tx = tid & 15, ty = tid >> 4;
    float acc[4][4] = {};
    gemm_TT64(g_P + 256, LDP, bt * 64, g_P, LDP, bi * 64, DD, acc, As, Bs, tid, tx, ty);
#pragma unroll
    for (int i = 0; i < 4; i++) {
        int t = bt * 64 + ty * 4 + i;
        const unsigned* Mrow = &g_M[t * 32];
        float4 vs;
        float* vp = (float*)&vs;
#pragma unroll
        for (int j = 0; j < 4; j++) {
            int ki = bi * 64 + tx * 4 + j;
            unsigned bit = (Mrow[ki >> 5] >> (ki & 31)) & 1u;
            vp[j] = bit ? acc[i][j] : 0.f;
        }
        *(float4*)&g_A[(size_t)t * TT + bi * 64 + tx * 4] = vs;
    }
}

// ---------------------------------------------------------------------------
// numer = A @ V (K truncated at diagonal), divide by clipped denom.
// grid (8 col-tiles of 32, 16 row-tiles of 64) = 128 blocks
// ---------------------------------------------------------------------------
__global__ void __launch_bounds__(256) numer_kernel() {
    int bn = blockIdx.x, bt = blockIdx.y;
    __shared__ float As[2][16][64], Bs[2][16][32];
    int tid = threadIdx.x, tx = tid & 15, ty = tid >> 4;
    float acc[4][2] = {};
    int K = (bt + 1) * 64;
    gemm_TN32(g_A, TT, bt * 64, g_P + 512, LDP, bn * 32, K, acc, As, Bs, tid, tx, ty);
#pragma unroll
    for (int i = 0; i < 4; i++) {
        int t = bt * 64 + ty * 4 + i;
        float inv = 1.f / fmaxf(g_den[t], 1e-5f);
        float2 vs;
        vs.x = acc[i][0] * inv; vs.y = acc[i][1] * inv;
        *(float2*)&g_O[(size_t)t * HH + bn * 32 + tx * 2] = vs;
    }
}

// ---------------------------------------------------------------------------
// MLP GEMMs, 64x32 tiles -> 128 blocks each.
// ---------------------------------------------------------------------------
__device__ __forceinline__ float mishf(float v) {
    float sp = (v > 20.f) ? v : log1pf(expf(v));
    return v * tanhf(sp);
}

template <int MODE>
__global__ void __launch_bounds__(256) mlp_kernel(const float* __restrict__ W,
                                                  const float* __restrict__ bias) {
    int bn = blockIdx.x, bm = blockIdx.y;
    __shared__ float As[2][16][64], Bs[2][16][32];
    int tid = threadIdx.x, tx = tid & 15, ty = tid >> 4;
    const float* Ain = (MODE == 0) ? g_O : (MODE == 1) ? g_H1 : g_H2;
    float* Cout = (MODE == 0) ? g_H1 : (MODE == 1) ? g_H2 : g_H3;
    float acc[4][2] = {};
    gemm_TT32(Ain, HH, bm * 64, W, HH, bn * 32, HH, acc, As, Bs, tid, tx, ty);
#pragma unroll
    for (int i = 0; i < 4; i++) {
        int t = bm * 64 + ty * 4 + i;
        float2 vs;
#pragma unroll
        for (int j = 0; j < 2; j++) {
            int c = bn * 32 + tx * 2 + j;
            float v = acc[i][j] + bias[c];
            if (MODE < 2) v = mishf(v);
            else          v += g_P[(size_t)t * LDP + 768 + c];
            ((float*)&vs)[j] = v;
        }
        *(float2*)&Cout[(size_t)t * HH + bn * 32 + tx * 2] = vs;
    }
}

// ---------------------------------------------------------------------------
// Per-row LayerNorm (256 threads = 1 row)
// ---------------------------------------------------------------------------
__global__ void ln_kernel(const float* __restrict__ w, const float* __restrict__ b,
                          float* __restrict__ out) {
    int row = blockIdx.x, tid = threadIdx.x;
    float v = g_H3[(size_t)row * HH + tid];
    __shared__ float sh[8];
    float s = v;
#pragma unroll
    for (int o = 16; o > 0; o >>= 1) s += __shfl_xor_sync(0xffffffffu, s, o);
    if ((tid & 31) == 0) sh[tid >> 5] = s;
    __syncthreads();
    float tot = 0.f;
#pragma unroll
    for (int i = 0; i < 8; i++) tot += sh[i];
    float mean = tot * (1.f / 256.f);
    float d = v - mean;
    float s2 = d * d;
#pragma unroll
    for (int o = 16; o > 0; o >>= 1) s2 += __shfl_xor_sync(0xffffffffu, s2, o);
    __syncthreads();
    if ((tid & 31) == 0) sh[tid >> 5] = s2;
    __syncthreads();
    float tot2 = 0.f;
#pragma unroll
    for (int i = 0; i < 8; i++) tot2 += sh[i];
    float var = tot2 * (1.f / 256.f);
    out[(size_t)row * HH + tid] = d * rsqrtf(var + 1e-5f) * w[tid] + b[tid];
}

// ---------------------------------------------------------------------------
extern "C" void kernel_launch(void* const* d_in, const int* in_sizes, int n_in,
                              void* d_out, int out_size) {
    const float* x     = (const float*)d_in[0];
    const int*   start = (const int*)d_in[3];
    const int*   done  = (const int*)d_in[4];
    const float* Wk = (const float*)d_in[5];
    const float* Wq = (const float*)d_in[6];
    const float* Wv = (const float*)d_in[7];
    const float* Ws = (const float*)d_in[8];
    const float* bskip = (const float*)d_in[9];
    const float* W1 = (const float*)d_in[10];
    const float* b1 = (const float*)d_in[11];
    const float* W2 = (const float*)d_in[12];
    const float* b2 = (const float*)d_in[13];
    const float* W3 = (const float*)d_in[14];
    const float* b3 = (const float*)d_in[15];
    const float* lnw = (const float*)d_in[16];
    const float* lnb = (const float*)d_in[17];
    float* out = (float*)d_out;

    scan_mask_kernel<<<1, 1024>>>(start, done);
    proj_kernel<<<dim3(16, 16), 256>>>(x, Wk, Wq, Wv, Ws, bskip);
    denom_kernel<<<128, 256>>>();
    scores_kernel<<<dim3(16, 16), 256>>>();
    numer_kernel<<<dim3(8, 16), 256>>>();
    mlp_kernel<0><<<dim3(8, 16), 256>>>(W1, b1);
    mlp_kernel<1><<<dim3(8, 16), 256>>>(W2, b2);
    mlp_kernel<2><<<dim3(8, 16), 256>>>(W3, b3);
    ln_kernel<<<1024, 256>>>(lnw, lnb, out);
}

// round 6
// speedup vs baseline: 1.4286x; 1.4286x over previous
#include <cuda_runtime.h>
#include <math.h>

#define TT   1024
#define DD   256
#define HH   256
#define LDP  1024

// Scratch (static device globals; no allocation)
__device__ float    g_P[TT*LDP];   // cols [0,256)=k(elu) [256,512)=q(elu) [512,768)=v [768,1024)=skip
__device__ float    g_A[TT*TT];    // masked scores (lower-tri tiles valid)
__device__ float    g_O[TT*HH];    // attention output (numer/denom)
__device__ float    g_H1[TT*HH];
__device__ float    g_H2[TT*HH];
__device__ float    g_H3[TT*HH];
__device__ unsigned g_M[TT*32];    // bit (ti,ki): coeff of kv_{ki+1} in scan result[ti+1]
__device__ float    g_den[TT];
__device__ float    g_ksum[TT], g_qsum[TT];

// Scan simulation scratch
__device__ unsigned g_Dm[2048*32];
__device__ unsigned g_Sm[2048*32];
__device__ int      g_Dg[2048];

// ---------------------------------------------------------------------------
// Exact simulation of jax.lax.associative_scan's recursive bracketing on
// 1024-bit coefficient masks. Also zeroes the rowsum accumulators.
// ---------------------------------------------------------------------------
__global__ void scan_mask_kernel(const int* __restrict__ start, const int* __restrict__ done) {
    const int n[11]   = {1025,512,256,128,64,32,16,8,4,2,1};
    const int off[11] = {0,1025,1537,1793,1921,1985,2017,2033,2041,2045,2047};
    int tid = threadIdx.x;

    if (tid < 1024) { g_ksum[tid] = 0.f; g_qsum[tid] = 0.f; }

    for (int idx = tid; idx < 1025*32; idx += blockDim.x) {
        int i = idx >> 5, w = idx & 31;
        unsigned m = 0;
        if (i > 0 && ((i-1) >> 5) == w) m = 1u << ((i-1) & 31);
        g_Dm[idx] = m;
        if (w == 0) g_Dg[i] = (start[i] ? 1 : 0) | (done[i] ? 2 : 0);
    }
    __syncthreads();

    for (int d = 0; d < 10; d++) {
        int nn = n[d+1];
        int src = off[d], dst = off[d+1];
        for (int idx = tid; idx < nn*32; idx += blockDim.x) {
            int i = idx >> 5, w = idx & 31;
            int gb = g_Dg[src + 2*i + 1];
            unsigned m = 0;
            if (gb & 1) m |= g_Dm[(src + 2*i    )*32 + w];
            if (gb & 2) m |= g_Dm[(src + 2*i + 1)*32 + w];
            g_Dm[(dst + i)*32 + w] = m;
            if (w == 0) g_Dg[dst + i] = gb;
        }
        __syncthreads();
    }

    for (int w = tid; w < 32; w += blockDim.x)
        g_Sm[off[10]*32 + w] = g_Dm[off[10]*32 + w];
    __syncthreads();

    for (int d = 9; d >= 0; d--) {
        int nd = n[d];
        int src = off[d], o = off[d+1];
        for (int idx = tid; idx < nd*32; idx += blockDim.x) {
            int pos = idx >> 5, w = idx & 31;
            unsigned m;
            if (pos == 0) {
                m = g_Dm[src*32 + w];
            } else if (pos & 1) {
                m = g_Sm[(o + (pos >> 1))*32 + w];
            } else {
                int i = (pos >> 1) - 1;
                int gb = g_Dg[src + pos];
                m = 0;
                if (gb & 1) m |= g_Sm[(o + i)*32 + w];
                if (gb & 2) m |= g_Dm[(src + pos)*32 + w];
            }
            g_Sm[(src + pos)*32 + w] = m;
        }
        __syncthreads();
    }

    for (int idx = tid; idx < 1024*32; idx += blockDim.x) {
        int t = idx >> 5, w = idx & 31;
        g_M[idx] = g_Sm[(t + 1)*32 + w];
    }
}

// ---------------------------------------------------------------------------
// GEMM cores: gmem double-buffer across K-steps AND register fragment
// double-buffer inside each K-step (LDS for kk+1 issued before kk's FMAs,
// giving ~36-cycle dependency distance > 29-cycle LDS latency).
// ---------------------------------------------------------------------------
__device__ __forceinline__ void microfma44(float acc[4][4], float4 a, float4 b) {
    acc[0][0] += a.x*b.x; acc[0][1] += a.x*b.y; acc[0][2] += a.x*b.z; acc[0][3] += a.x*b.w;
    acc[1][0] += a.y*b.x; acc[1][1] += a.y*b.y; acc[1][2] += a.y*b.z; acc[1][3] += a.y*b.w;
    acc[2][0] += a.z*b.x; acc[2][1] += a.z*b.y; acc[2][2] += a.z*b.z; acc[2][3] += a.z*b.w;
    acc[3][0] += a.w*b.x; acc[3][1] += a.w*b.y; acc[3][2] += a.w*b.z; acc[3][3] += a.w*b.w;
}
__device__ __forceinline__ void microfma42(float acc[4][2], float4 a, float2 b) {
    acc[0][0] += a.x*b.x; acc[0][1] += a.x*b.y;
    acc[1][0] += a.y*b.x; acc[1][1] += a.y*b.y;
    acc[2][0] += a.z*b.x; acc[2][1] += a.z*b.y;
    acc[3][0] += a.w*b.x; acc[3][1] += a.w*b.y;
}

// C[64x64] = A[64xK] * B[64xK]^T  (both k-contiguous rows)
__device__ __forceinline__ void gemm_TT64(
    const float* __restrict__ A, int lda, int m0,
    const float* __restrict__ B, int ldb, int n0,
    int K, float acc[4][4],
    float (*As)[16][64], float (*Bs)[16][64],
    int tid, int tx, int ty)
{
    int row = tid >> 2, c4 = (tid & 3) << 2;
    const float* pA = A + (size_t)(m0 + row) * lda + c4;
    const float* pB = B + (size_t)(n0 + row) * ldb + c4;
    float4 av = *(const float4*)pA;
    float4 bv = *(const float4*)pB;
    int buf = 0;
    As[0][c4+0][row]=av.x; As[0][c4+1][row]=av.y; As[0][c4+2][row]=av.z; As[0][c4+3][row]=av.w;
    Bs[0][c4+0][row]=bv.x; Bs[0][c4+1][row]=bv.y; Bs[0][c4+2][row]=bv.z; Bs[0][c4+3][row]=bv.w;
    __syncthreads();
    for (int k0 = 16; k0 <= K; k0 += 16) {
        bool more = (k0 < K);
        if (more) { av = *(const float4*)(pA + k0); bv = *(const float4*)(pB + k0); }
        float4 a_cur = *(const float4*)&As[buf][0][ty*4];
        float4 b_cur = *(const float4*)&Bs[buf][0][tx*4];
#pragma unroll
        for (int kk = 0; kk < 16; kk++) {
            float4 a_nxt = a_cur, b_nxt = b_cur;
            if (kk < 15) {
                a_nxt = *(const float4*)&As[buf][kk+1][ty*4];
                b_nxt = *(const float4*)&Bs[buf][kk+1][tx*4];
            }
            microfma44(acc, a_cur, b_cur);
            a_cur = a_nxt; b_cur = b_nxt;
        }
        if (more) {
            int nb = buf ^ 1;
            As[nb][c4+0][row]=av.x; As[nb][c4+1][row]=av.y; As[nb][c4+2][row]=av.z; As[nb][c4+3][row]=av.w;
            Bs[nb][c4+0][row]=bv.x; Bs[nb][c4+1][row]=bv.y; Bs[nb][c4+2][row]=bv.z; Bs[nb][c4+3][row]=bv.w;
            __syncthreads();
            buf = nb;
        }
    }
}

// C[64x32] = A[64xK] * B[32xK]^T   (both k-contiguous rows)
__device__ __forceinline__ void gemm_TT32(
    const float* __restrict__ A, int lda, int m0,
    const float* __restrict__ B, int ldb, int n0,
    int K, float acc[4][2],
    float (*As)[16][64], float (*Bs)[16][32],
    int tid, int tx, int ty)
{
    int rowA = tid >> 2, c4 = (tid & 3) << 2;
    int rowB = tid >> 2;   // only tid<128 loads B (rows 0..31)
    const float* pA = A + (size_t)(m0 + rowA) * lda + c4;
    const float* pB = B + (size_t)(n0 + rowB) * ldb + c4;
    float4 av = *(const float4*)pA;
    float4 bv;
    if (tid < 128) bv = *(const float4*)pB;
    int buf = 0;
    As[0][c4+0][rowA]=av.x; As[0][c4+1][rowA]=av.y; As[0][c4+2][rowA]=av.z; As[0][c4+3][rowA]=av.w;
    if (tid < 128) {
        Bs[0][c4+0][rowB]=bv.x; Bs[0][c4+1][rowB]=bv.y; Bs[0][c4+2][rowB]=bv.z; Bs[0][c4+3][rowB]=bv.w;
    }
    __syncthreads();
    for (int k0 = 16; k0 <= K; k0 += 16) {
        bool more = (k0 < K);
        if (more) {
            av = *(const float4*)(pA + k0);
            if (tid < 128) bv = *(const float4*)(pB + k0);
        }
        float4 a_cur = *(const float4*)&As[buf][0][ty*4];
        float2 b_cur = *(const float2*)&Bs[buf][0][tx*2];
#pragma unroll
        for (int kk = 0; kk < 16; kk++) {
            float4 a_nxt = a_cur; float2 b_nxt = b_cur;
            if (kk < 15) {
                a_nxt = *(const float4*)&As[buf][kk+1][ty*4];
                b_nxt = *(const float2*)&Bs[buf][kk+1][tx*2];
            }
            microfma42(acc, a_cur, b_cur);
            a_cur = a_nxt; b_cur = b_nxt;
        }
        if (more) {
            int nb = buf ^ 1;
            As[nb][c4+0][rowA]=av.x; As[nb][c4+1][rowA]=av.y; As[nb][c4+2][rowA]=av.z; As[nb][c4+3][rowA]=av.w;
            if (tid < 128) {
                Bs[nb][c4+0][rowB]=bv.x; Bs[nb][c4+1][rowB]=bv.y; Bs[nb][c4+2][rowB]=bv.z; Bs[nb][c4+3][rowB]=bv.w;
            }
            __syncthreads();
            buf = nb;
        }
    }
}

// C[64x32] = A[64xK] * B[Kx32]   (B row-major k x n)
__device__ __forceinline__ void gemm_TN32(
    const float* __restrict__ A, int lda, int m0,
    const float* __restrict__ B, int ldb, int n0,
    int K, float acc[4][2],
    float (*As)[16][64], float (*Bs)[16][32],
    int tid, int tx, int ty)
{
    int rowA = tid >> 2, c4 = (tid & 3) << 2;
    int kB = tid >> 3, cB = (tid & 7) << 2;  // tid<128: 16 k-rows x 32 cols
    const float* pA = A + (size_t)(m0 + rowA) * lda + c4;
    const float* pB = B + (size_t)kB * ldb + n0 + cB;
    float4 av = *(const float4*)pA;
    float4 bv;
    if (tid < 128) bv = *(const float4*)pB;
    int buf = 0;
    As[0][c4+0][rowA]=av.x; As[0][c4+1][rowA]=av.y; As[0][c4+2][rowA]=av.z; As[0][c4+3][rowA]=av.w;
    if (tid < 128) *(float4*)&Bs[0][kB][cB] = bv;
    __syncthreads();
    for (int k0 = 16; k0 <= K; k0 += 16) {
        bool more = (k0 < K);
        if (more) {
            av = *(const float4*)(pA + k0);
            if (tid < 128) bv = *(const float4*)(pB + (size_t)k0 * ldb);
        }
        float4 a_cur = *(const float4*)&As[buf][0][ty*4];
        float2 b_cur = *(const float2*)&Bs[buf][0][tx*2];
#pragma unroll
        for (int kk = 0; kk < 16; kk++) {
            float4 a_nxt = a_cur; float2 b_nxt = b_cur;
            if (kk < 15) {
                a_nxt = *(const float4*)&As[buf][kk+1][ty*4];
                b_nxt = *(const float2*)&Bs[buf][kk+1][tx*2];
            }
            microfma42(acc, a_cur, b_cur);
            a_cur = a_nxt; b_cur = b_nxt;
        }
        if (more) {
            int nb = buf ^ 1;
            As[nb][c4+0][rowA]=av.x; As[nb][c4+1][rowA]=av.y; As[nb][c4+2][rowA]=av.z; As[nb][c4+3][rowA]=av.w;
            if (tid < 128) *(float4*)&Bs[nb][kB][cB] = bv;
            __syncthreads();
            buf = nb;
        }
    }
}

// ---------------------------------------------------------------------------
// Projections + fused k/q row sums.
// ---------------------------------------------------------------------------
__global__ void __launch_bounds__(256) proj_kernel(
    const float* __restrict__ X,
    const float* __restrict__ Wk, const float* __restrict__ Wq,
    const float* __restrict__ Wv, const float* __restrict__ Ws,
    const float* __restrict__ bskip)
{
    __shared__ float As[2][16][64], Bs[2][16][64];
    __shared__ float red[64][17];
    int tid = threadIdx.x, tx = tid & 15, ty = tid >> 4;
    int bx = blockIdx.x, by = blockIdx.y;
    int wsel = bx >> 2;
    const float* W = (wsel == 0) ? Wk : (wsel == 1) ? Wq : (wsel == 2) ? Wv : Ws;
    int n0 = (bx & 3) * 64;
    int m0 = by * 64;
    float acc[4][4] = {};
    gemm_TT64(X, DD, m0, W, DD, n0, DD, acc, As, Bs, tid, tx, ty);

    float rs[4] = {0.f, 0.f, 0.f, 0.f};
#pragma unroll
    for (int i = 0; i < 4; i++) {
        int t = m0 + ty * 4 + i;
        float4 vs;
        float* vp = (float*)&vs;
#pragma unroll
        for (int j = 0; j < 4; j++) {
            int c = n0 + tx * 4 + j;
            float v = acc[i][j];
            if (wsel < 2) v = (v > 0.f) ? v : expm1f(v);     // elu
            if (wsel == 3) v += bskip[c];
            vp[j] = v;
            rs[i] += v;
        }
        *(float4*)&g_P[(size_t)t * LDP + wsel * 256 + n0 + tx * 4] = vs;
    }
    if (wsel < 2) {
        __syncthreads();
#pragma unroll
        for (int i = 0; i < 4; i++) red[ty * 4 + i][tx] = rs[i];
        __syncthreads();
        if (tid < 64) {
            float s = 0.f;
#pragma unroll
            for (int x = 0; x < 16; x++) s += red[tid][x];
            atomicAdd((wsel == 0) ? &g_ksum[m0 + tid] : &g_qsum[m0 + tid], s);
        }
    }
}

// ---------------------------------------------------------------------------
// denom[t] = qsum[t] * sum_j mask(t,j)*ksum[j].  ksum staged in SMEM.
// ---------------------------------------------------------------------------
__global__ void denom_kernel() {
    __shared__ float ks[1024];
    int tid = threadIdx.x;
    for (int i = tid; i < 1024; i += 256) ks[i] = g_ksum[i];
    __syncthreads();
    int row  = blockIdx.x * 8 + (tid >> 5);
    int lane = tid & 31;
    unsigned bits = g_M[row * 32 + lane];
    float s = 0.f;
    while (bits) {
        int b = __ffs(bits) - 1;
        bits &= bits - 1;
        s += ks[lane * 32 + b];
    }
#pragma unroll
    for (int o = 16; o > 0; o >>= 1) s += __shfl_xor_sync(0xffffffffu, s, o);
    if (lane == 0) g_den[row] = s * g_qsum[row];
}

// ---------------------------------------------------------------------------
// Masked scores A = (Q K^T) * M. Linearized lower-triangular grid: 136 blocks.
// ---------------------------------------------------------------------------
__global__ void __launch_bounds__(256) scores_kernel() {
    int l = blockIdx.x;
    int bt = (int)((sqrtf(8.f * l + 1.f) - 1.f) * 0.5f);
    while ((bt + 1) * (bt + 2) / 2 <= l) bt++;
    while (bt * (bt + 1) / 2 > l) bt--;
    int bi = l - bt * (bt + 1) / 2;

    __shared__ float As[2][16][64], Bs[2][16][64];
    int tid = threadIdx.x, tx = tid & 15, ty = tid >> 4;
    float acc[4][4] = {};
    gemm_TT64(g_P + 256, LDP, bt * 64, g_P, LDP, bi * 64, DD, acc, As, Bs, tid, tx, ty);
#pragma unroll
    for (int i = 0; i < 4; i++) {
        int t = bt * 64 + ty * 4 + i;
        const unsigned* Mrow = &g_M[t * 32];
        float4 vs;
        float* vp = (float*)&vs;
#pragma unroll
        for (int j = 0; j < 4; j++) {
            int ki = bi * 64 + tx * 4 + j;
            unsigned bit = (Mrow[ki >> 5] >> (ki & 31)) & 1u;
            vp[j] = bit ? acc[i][j] : 0.f;
        }
        *(float4*)&g_A[(size_t)t * TT + bi * 64 + tx * 4] = vs;
    }
}

// ---------------------------------------------------------------------------
// numer = A @ V (K truncated at diagonal), divide by clipped denom.
// grid (8 col-tiles of 32, 16 row-tiles of 64) = 128 blocks
// ---------------------------------------------------------------------------
__global__ void __launch_bounds__(256) numer_kernel() {
    int bn = blockIdx.x, bt = blockIdx.y;
    __shared__ float As[2][16][64], Bs[2][16][32];
    int tid = threadIdx.x, tx = tid & 15, ty = tid >> 4;
    float acc[4][2] = {};
    int K = (bt + 1) * 64;
    gemm_TN32(g_A, TT, bt * 64, g_P + 512, LDP, bn * 32, K, acc, As, Bs, tid, tx, ty);
#pragma unroll
    for (int i = 0; i < 4; i++) {
        int t = bt * 64 + ty * 4 + i;
        float inv = 1.f / fmaxf(g_den[t], 1e-5f);
        float2 vs;
        vs.x = acc[i][0] * inv; vs.y = acc[i][1] * inv;
        *(float2*)&g_O[(size_t)t * HH + bn * 32 + tx * 2] = vs;
    }
}

// ---------------------------------------------------------------------------
// MLP GEMMs, 64x32 tiles -> 128 blocks each.
// ---------------------------------------------------------------------------
__device__ __forceinline__ float mishf(float v) {
    float sp = (v > 20.f) ? v : log1pf(expf(v));
    return v * tanhf(sp);
}

template <int MODE>
__global__ void __launch_bounds__(256) mlp_kernel(const float* __restrict__ W,
                                                  const float* __restrict__ bias) {
    int bn = blockIdx.x, bm = blockIdx.y;
    __shared__ float As[2][16][64], Bs[2][16][32];
    int tid = threadIdx.x, tx = tid & 15, ty = tid >> 4;
    const float* Ain = (MODE == 0) ? g_O : (MODE == 1) ? g_H1 : g_H2;
    float* Cout = (MODE == 0) ? g_H1 : (MODE == 1) ? g_H2 : g_H3;
    float acc[4][2] = {};
    gemm_TT32(Ain, HH, bm * 64, W, HH, bn * 32, HH, acc, As, Bs, tid, tx, ty);
#pragma unroll
    for (int i = 0; i < 4; i++) {
        int t = bm * 64 + ty * 4 + i;
        float2 vs;
#pragma unroll
        for (int j = 0; j < 2; j++) {
            int c = bn * 32 + tx * 2 + j;
            float v = acc[i][j] + bias[c];
            if (MODE < 2) v = mishf(v);
            else          v += g_P[(size_t)t * LDP + 768 + c];
            ((float*)&vs)[j] = v;
        }
        *(float2*)&Cout[(size_t)t * HH + bn * 32 + tx * 2] = vs;
    }
}

// ---------------------------------------------------------------------------
// Per-row LayerNorm (256 threads = 1 row)
// ---------------------------------------------------------------------------
__global__ void ln_kernel(const float* __restrict__ w, const float* __restrict__ b,
                          float* __restrict__ out) {
    int row = blockIdx.x, tid = threadIdx.x;
    float v = g_H3[(size_t)row * HH + tid];
    __shared__ float sh[8];
    float s = v;
#pragma unroll
    for (int o = 16; o > 0; o >>= 1) s += __shfl_xor_sync(0xffffffffu, s, o);
    if ((tid & 31) == 0) sh[tid >> 5] = s;
    __syncthreads();
    float tot = 0.f;
#pragma unroll
    for (int i = 0; i < 8; i++) tot += sh[i];
    float mean = tot * (1.f / 256.f);
    float d = v - mean;
    float s2 = d * d;
#pragma unroll
    for (int o = 16; o > 0; o >>= 1) s2 += __shfl_xor_sync(0xffffffffu, s2, o);
    __syncthreads();
    if ((tid & 31) == 0) sh[tid >> 5] = s2;
    __syncthreads();
    float tot2 = 0.f;
#pragma unroll
    for (int i = 0; i < 8; i++) tot2 += sh[i];
    float var = tot2 * (1.f / 256.f);
    out[(size_t)row * HH + tid] = d * rsqrtf(var + 1e-5f) * w[tid] + b[tid];
}

// ---------------------------------------------------------------------------
extern "C" void kernel_launch(void* const* d_in, const int* in_sizes, int n_in,
                              void* d_out, int out_size) {
    const float* x     = (const float*)d_in[0];
    const int*   start = (const int*)d_in[3];
    const int*   done  = (const int*)d_in[4];
    const float* Wk = (const float*)d_in[5];
    const float* Wq = (const float*)d_in[6];
    const float* Wv = (const float*)d_in[7];
    const float* Ws = (const float*)d_in[8];
    const float* bskip = (const float*)d_in[9];
    const float* W1 = (const float*)d_in[10];
    const float* b1 = (const float*)d_in[11];
    const float* W2 = (const float*)d_in[12];
    const float* b2 = (const float*)d_in[13];
    const float* W3 = (const float*)d_in[14];
    const float* b3 = (const float*)d_in[15];
    const float* lnw = (const float*)d_in[16];
    const float* lnb = (const float*)d_in[17];
    float* out = (float*)d_out;

    scan_mask_kernel<<<1, 1024>>>(start, done);
    proj_kernel<<<dim3(16, 16), 256>>>(x, Wk, Wq, Wv, Ws, bskip);
    denom_kernel<<<128, 256>>>();
    scores_kernel<<<136, 256>>>();
    numer_kernel<<<dim3(8, 16), 256>>>();
    mlp_kernel<0><<<dim3(8, 16), 256>>>(W1, b1);
    mlp_kernel<1><<<dim3(8, 16), 256>>>(W2, b2);
    mlp_kernel<2><<<dim3(8, 16), 256>>>(W3, b3);
    ln_kernel<<<1024, 256>>>(lnw, lnb, out);
}